// round 16
// baseline (speedup 1.0000x reference)
#include <cuda_runtime.h>

#define NNODES 4096
#define C      128
#define E      10
#define NI     9
#define NM     9      // 1+3+5 output comps
#define K3     30
#define K2     12
#define K1     4
#define NT3    165    // sorted triples p<=q<=r of 9
#define NT2    45     // sorted pairs
#define MROW   12     // padded m-row stride (ull) -> 96B rows, 16B-aligned
#define OUTW   1152   // C*(1+3+5)
#define NORMF  0.08838834764831845f  // 1/sqrt(128)
#define TC     24     // t-chunk size for c3 fold
#define NCH    7      // ceil(165/24)

typedef unsigned long long ull;

// ---------- packed f32x2 helpers ----------
__device__ __forceinline__ ull fma2(ull a, ull b, ull c) {
    ull d; asm("fma.rn.f32x2 %0, %1, %2, %3;" : "=l"(d) : "l"(a), "l"(b), "l"(c)); return d;
}
__device__ __forceinline__ ull mul2(ull a, ull b) {
    ull d; asm("mul.rn.f32x2 %0, %1, %2;" : "=l"(d) : "l"(a), "l"(b)); return d;
}
__device__ __forceinline__ ull pack2(float a, float b) {
    ull r; asm("mov.b64 %0, {%1,%2};" : "=l"(r) : "r"(__float_as_uint(a)), "r"(__float_as_uint(b))); return r;
}
__device__ __forceinline__ ull dup2(float v) { return pack2(v, v); }
__device__ __forceinline__ void unpack2(ull v, float& a, float& b) {
    unsigned lo, hi; asm("mov.b64 {%0,%1}, %2;" : "=r"(lo), "=r"(hi) : "l"(v));
    a = __uint_as_float(lo); b = __uint_as_float(hi);
}

// ---------- device scratch (static) ----------
__device__ int   g_cnt[E];
__device__ int   g_list[E * NNODES];
__device__ float g_C3[E * C * NM * NT3];
__device__ float g_C2[E * C * NM * NT2];
__device__ float g_C1[E * C * NM * NI];
__device__ float g_res[NNODES * C * NM];   // [b][c][m]

__device__ __forceinline__ void m_to_ld(int m, int& L, int& d) {
    if (m == 0)      { L = 0; d = 0; }
    else if (m < 4)  { L = 1; d = m - 1; }
    else             { L = 2; d = m - 4; }
}

// ---------- 1: fused prep — bucket (10) + chunked c3 fold (630) + c21 fold (90) ----------
__global__ void __launch_bounds__(256) k_prep(
    const float* __restrict__ attrs,
    const float* __restrict__ A0, const float* __restrict__ A1, const float* __restrict__ A2,   // U3
    const float* __restrict__ B0, const float* __restrict__ B1, const float* __restrict__ B2,   // U2
    const float* __restrict__ U1_0, const float* __restrict__ U1_1, const float* __restrict__ U1_2,
    const float* __restrict__ W0, const float* __restrict__ W1, const float* __restrict__ W2,   // W3
    const float* __restrict__ W2_0, const float* __restrict__ W2_1, const float* __restrict__ W2_2,
    const float* __restrict__ W1_0, const float* __restrict__ W1_1, const float* __restrict__ W1_2) {
    __shared__ int   tp[NT3], tq[NT3], tr[NT3];
    __shared__ float sU[TC * K3];     // 2.9 KB (chunked)
    __shared__ int   pp[NT2], pq[NT2];
    __shared__ float sU2[NT2 * K2];
    __shared__ int   scnt;
    int bid = blockIdx.x;
    int tid = threadIdx.x;

    if (bid < E) {
        // ---- bucket: block e selects its own nodes ----
        int e = bid;
        if (tid == 0) scnt = 0;
        __syncthreads();
        for (int b = tid; b < NNODES; b += 256) {
            const float* a = attrs + b * E;
            int am = 0; float best = a[0];
            #pragma unroll
            for (int j = 1; j < E; j++) if (a[j] > best) { best = a[j]; am = j; }
            if (am == e) {
                int pos = atomicAdd(&scnt, 1);
                g_list[e * NNODES + pos] = b;
            }
        }
        __syncthreads();
        if (tid == 0) g_cnt[e] = scnt;
        return;
    }
    if (bid < E + NM * E * NCH) {
        // ---- chunked c3 fold: block = (m, e, chunk) ----
        int w = bid - E;
        int chunk = w % NCH;
        int me = w / NCH;
        int m = me % NM, e = me / NM, L, d; m_to_ld(m, L, d);
        int t0 = chunk * TC;
        int tend = (t0 + TC < NT3) ? (t0 + TC) : NT3;
        if (tid == 0) {
            int t = 0;
            for (int q = 0; q < NI; q++)
                for (int r = q; r < NI; r++)
                    for (int p = 0; p <= q; p++) { tp[t] = p; tq[t] = q; tr[t] = r; t++; }
        }
        __syncthreads();
        const float* U = (L == 0) ? A0 : ((L == 1) ? A1 : A2);
        int nsym = (tend - t0) * K3;
        for (int idx = tid; idx < nsym; idx += 256) {
            int t = t0 + idx / K3, k = idx % K3;
            int p = tp[t], q = tq[t], r = tr[t];
            float s = U[(((d*NI + p)*NI + q)*NI + r)*K3 + k]
                    + U[(((d*NI + p)*NI + r)*NI + q)*K3 + k]
                    + U[(((d*NI + q)*NI + p)*NI + r)*K3 + k]
                    + U[(((d*NI + q)*NI + r)*NI + p)*K3 + k]
                    + U[(((d*NI + r)*NI + p)*NI + q)*K3 + k]
                    + U[(((d*NI + r)*NI + q)*NI + p)*K3 + k];
            float div = (p == r) ? 6.f : ((p == q || q == r) ? 2.f : 1.f);
            sU[idx] = s / div;
        }
        __syncthreads();
        int c = tid & 127, sub = tid >> 7;
        const float* W = ((L == 0) ? W0 : ((L == 1) ? W1 : W2)) + e * K3 * C;
        float w3[K3];
        #pragma unroll
        for (int k = 0; k < K3; k++) w3[k] = W[k * C + c];
        float* dst = &g_C3[((e*C + c)*NM + m)*NT3];
        for (int t = t0 + sub; t < tend; t += 2) {
            float a = 0.f;
            #pragma unroll
            for (int k = 0; k < K3; k++) a += sU[(t - t0)*K3 + k] * w3[k];
            dst[t] = a;
        }
        return;
    }
    {
        // ---- c2 + c1 fold ----
        int w = bid - E - NM * E * NCH;
        int m = w % NM, e = w / NM, L, d; m_to_ld(m, L, d);
        if (tid == 0) {
            int s = 0;
            for (int q = 0; q < NI; q++)
                for (int p = 0; p <= q; p++) { pp[s] = p; pq[s] = q; s++; }
        }
        __syncthreads();
        const float* U2 = (L == 0) ? B0 : ((L == 1) ? B1 : B2);
        for (int idx = tid; idx < NT2 * K2; idx += 256) {
            int s = idx / K2, k = idx % K2;
            int p = pp[s], q = pq[s];
            float v = U2[((d*NI + p)*NI + q)*K2 + k];
            if (p != q) v += U2[((d*NI + q)*NI + p)*K2 + k];
            sU2[idx] = v;
        }
        __syncthreads();
        int c = tid & 127, sub = tid >> 7;
        const float* Wq = ((L == 0) ? W2_0 : ((L == 1) ? W2_1 : W2_2)) + e * K2 * C;
        float w2[K2];
        #pragma unroll
        for (int k = 0; k < K2; k++) w2[k] = Wq[k * C + c];
        float* d2 = &g_C2[((e*C + c)*NM + m)*NT2];
        for (int s = sub; s < NT2; s += 2) {
            float a = 0.f;
            #pragma unroll
            for (int k = 0; k < K2; k++) a += sU2[s*K2 + k] * w2[k];
            d2[s] = a;
        }
        if (sub == 0) {
            const float* Wl = ((L == 0) ? W1_0 : ((L == 1) ? W1_1 : W1_2)) + e * K1 * C;
            const float* U1 = ((L == 0) ? U1_0 : ((L == 1) ? U1_1 : U1_2)) + d * NI * K1;
            float w1[K1];
            #pragma unroll
            for (int k = 0; k < K1; k++) w1[k] = Wl[k * C + c];
            float* d1 = &g_C1[((e*C + c)*NM + m)*NI];
            #pragma unroll
            for (int i = 0; i < NI; i++) {
                float a = 0.f;
                #pragma unroll
                for (int k = 0; k < K1; k++) a += U1[i*K1 + k] * w1[k];
                d1[i] = a;
            }
        }
    }
}

// ---------- 2: main contraction — unchanged from R15 (passing) ----------
__global__ void __launch_bounds__(256, 2) k_main(const float* __restrict__ nf) {
    __shared__ __align__(16) ull s3t[NT3 * MROW];  // 15.5 KB
    __shared__ __align__(16) ull s2t[NT2 * MROW];  //  4.2 KB
    __shared__ __align__(16) ull s1t[NI  * MROW];  //  0.84 KB
    int c = blockIdx.x, e = blockIdx.y;
    {
        const float* g3 = g_C3 + (e*C + c) * NM * NT3;
        const float* g2 = g_C2 + (e*C + c) * NM * NT2;
        const float* g1 = g_C1 + (e*C + c) * NM * NI;
        for (int i = threadIdx.x; i < NM*NT3; i += 256) {
            int m = i / NT3, t = i % NT3;
            s3t[t*MROW + m] = dup2(g3[i]);
        }
        for (int i = threadIdx.x; i < NM*NT2; i += 256) {
            int m = i / NT2, s = i % NT2;
            s2t[s*MROW + m] = dup2(g2[i]);
        }
        for (int i = threadIdx.x; i < NM*NI; i += 256) {
            int m = i / NI, p = i % NI;
            s1t[p*MROW + m] = dup2(g1[i]);
        }
    }
    __syncthreads();
    int cnt = g_cnt[e];
    const int* lst = g_list + e * NNODES;

    for (int base = 0; base < cnt; base += 512) {
        int i0 = base + threadIdx.x;
        bool v0 = i0 < cnt, v1 = (i0 + 256) < cnt;
        int b0 = v0 ? lst[i0]       : 0;
        int b1 = v1 ? lst[i0 + 256] : 0;
        const float* p0 = nf + (b0*C + c) * NI;
        const float* p1 = nf + (b1*C + c) * NI;

        ull xa[9];
        #pragma unroll
        for (int n = 0; n < 9; n++)
            xa[n] = pack2(v0 ? p0[n] : 0.f, v1 ? p1[n] : 0.f);

        ull acc[9];
        #pragma unroll
        for (int m = 0; m < 9; m++) acc[m] = 0ull;

        // linear
        #pragma unroll
        for (int p = 0; p < 9; p++) {
            const ulonglong2* cp = reinterpret_cast<const ulonglong2*>(&s1t[p*MROW]);
            ulonglong2 c01 = cp[0], c23 = cp[1], c45 = cp[2], c67 = cp[3];
            ull c8 = s1t[p*MROW + 8];
            ull mo = xa[p];
            acc[0] = fma2(c01.x, mo, acc[0]); acc[1] = fma2(c01.y, mo, acc[1]);
            acc[2] = fma2(c23.x, mo, acc[2]); acc[3] = fma2(c23.y, mo, acc[3]);
            acc[4] = fma2(c45.x, mo, acc[4]); acc[5] = fma2(c45.y, mo, acc[5]);
            acc[6] = fma2(c67.x, mo, acc[6]); acc[7] = fma2(c67.y, mo, acc[7]);
            acc[8] = fma2(c8,    mo, acc[8]);
        }
        // quadratic
        {
            int s = 0;
            #pragma unroll
            for (int q = 0; q < 9; q++)
                #pragma unroll
                for (int p = 0; p <= q; p++) {
                    ull mo = mul2(xa[p], xa[q]);
                    const ulonglong2* cp = reinterpret_cast<const ulonglong2*>(&s2t[s*MROW]);
                    ulonglong2 c01 = cp[0], c23 = cp[1], c45 = cp[2], c67 = cp[3];
                    ull c8 = s2t[s*MROW + 8];
                    acc[0] = fma2(c01.x, mo, acc[0]); acc[1] = fma2(c01.y, mo, acc[1]);
                    acc[2] = fma2(c23.x, mo, acc[2]); acc[3] = fma2(c23.y, mo, acc[3]);
                    acc[4] = fma2(c45.x, mo, acc[4]); acc[5] = fma2(c45.y, mo, acc[5]);
                    acc[6] = fma2(c67.x, mo, acc[6]); acc[7] = fma2(c67.y, mo, acc[7]);
                    acc[8] = fma2(c8,    mo, acc[8]);
                    s++;
                }
        }
        // cubic
        {
            int t = 0;
            #pragma unroll
            for (int q = 0; q < 9; q++)
                #pragma unroll
                for (int r = q; r < 9; r++) {
                    ull w = mul2(xa[q], xa[r]);
                    #pragma unroll
                    for (int p = 0; p <= q; p++) {
                        ull mo = mul2(xa[p], w);
                        const ulonglong2* cp = reinterpret_cast<const ulonglong2*>(&s3t[t*MROW]);
                        ulonglong2 c01 = cp[0], c23 = cp[1], c45 = cp[2], c67 = cp[3];
                        ull c8 = s3t[t*MROW + 8];
                        acc[0] = fma2(c01.x, mo, acc[0]); acc[1] = fma2(c01.y, mo, acc[1]);
                        acc[2] = fma2(c23.x, mo, acc[2]); acc[3] = fma2(c23.y, mo, acc[3]);
                        acc[4] = fma2(c45.x, mo, acc[4]); acc[5] = fma2(c45.y, mo, acc[5]);
                        acc[6] = fma2(c67.x, mo, acc[6]); acc[7] = fma2(c67.y, mo, acc[7]);
                        acc[8] = fma2(c8,    mo, acc[8]);
                        t++;
                    }
                }
        }
        // store res[b][c][m]
        #pragma unroll
        for (int m = 0; m < 9; m++) {
            float f0, f1;
            unpack2(acc[m], f0, f1);
            if (v0) g_res[(b0*C + c)*NM + m] = f0;
            if (v1) g_res[(b1*C + c)*NM + m] = f1;
        }
    }
}

// ---------- 3: channel mix — 16 nodes/block via two independent 128-thread halves ----------
__global__ void __launch_bounds__(256) k_mix(const float* __restrict__ lin0,
                                             const float* __restrict__ lin1,
                                             const float* __restrict__ lin2,
                                             const float* __restrict__ sc,
                                             float* __restrict__ out) {
    __shared__ ull sres[2 * 64 * 9 * 4];   // per-half [c_local*9+m][j], 36 KB
    int f = threadIdx.x & 127;
    int h = threadIdx.x >> 7;
    int bb = blockIdx.x * 16 + h * 8;
    ull* sr = &sres[h * 2304];
    ull acc[9][4];
    #pragma unroll
    for (int m = 0; m < 9; m++)
        #pragma unroll
        for (int j = 0; j < 4; j++) acc[m][j] = 0ull;

    for (int ct = 0; ct < 2; ct++) {
        int c0 = ct * 64;
        __syncthreads();
        for (int idx = f; idx < 64*9*4; idx += 128) {
            int j  = idx / 576;
            int cm = idx % 576;
            int n0 = bb + 2*j;
            float a = g_res[(n0    *C + c0)*NM + cm];
            float b = g_res[((n0+1)*C + c0)*NM + cm];
            sr[cm*4 + j] = pack2(a, b);
        }
        __syncthreads();
        for (int cl = 0; cl < 64; cl++) {
            int cc = c0 + cl;
            ull l0 = dup2(lin0[cc*C + f]);
            ull l1 = dup2(lin1[cc*C + f]);
            ull l2 = dup2(lin2[cc*C + f]);
            #pragma unroll
            for (int m = 0; m < 9; m++) {
                ull lv = (m == 0) ? l0 : ((m < 4) ? l1 : l2);
                const ulonglong2* sp = reinterpret_cast<const ulonglong2*>(&sr[(cl*9 + m)*4]);
                ulonglong2 va = sp[0];
                ulonglong2 vb = sp[1];
                acc[m][0] = fma2(lv, va.x, acc[m][0]);
                acc[m][1] = fma2(lv, va.y, acc[m][1]);
                acc[m][2] = fma2(lv, vb.x, acc[m][2]);
                acc[m][3] = fma2(lv, vb.y, acc[m][3]);
            }
        }
    }
    #pragma unroll
    for (int m = 0; m < 9; m++) {
        int col = (m == 0) ? f : ((m < 4) ? (128 + f*3 + (m-1)) : (512 + f*5 + (m-4)));
        #pragma unroll
        for (int j = 0; j < 4; j++) {
            float v0, v1; unpack2(acc[m][j], v0, v1);
            int n0 = bb + 2*j;
            out[n0*OUTW + col]     = v0 * NORMF + sc[n0*OUTW + col];
            out[(n0+1)*OUTW + col] = v1 * NORMF + sc[(n0+1)*OUTW + col];
        }
    }
}

extern "C" void kernel_launch(void* const* d_in, const int* in_sizes, int n_in,
                              void* d_out, int out_size) {
    (void)in_sizes; (void)n_in; (void)out_size;
    const float* nf    = (const float*)d_in[0];
    const float* sc    = (const float*)d_in[1];
    const float* attrs = (const float*)d_in[2];
    const float* U3[3]; const float* U2[3]; const float* U1[3];
    const float* W3[3]; const float* W2[3]; const float* W1[3]; const float* LN[3];
    for (int L = 0; L < 3; L++) {
        int b = 3 + 7*L;
        U3[L] = (const float*)d_in[b+0];
        U2[L] = (const float*)d_in[b+1];
        U1[L] = (const float*)d_in[b+2];
        W3[L] = (const float*)d_in[b+3];
        W2[L] = (const float*)d_in[b+4];
        W1[L] = (const float*)d_in[b+5];
        LN[L] = (const float*)d_in[b+6];
    }
    float* out = (float*)d_out;

    k_prep<<<E + NM * E * NCH + NM * E, 256>>>(attrs,
                                    U3[0], U3[1], U3[2],
                                    U2[0], U2[1], U2[2],
                                    U1[0], U1[1], U1[2],
                                    W3[0], W3[1], W3[2],
                                    W2[0], W2[1], W2[2],
                                    W1[0], W1[1], W1[2]);
    k_main<<<dim3(C, E), 256>>>(nf);
    k_mix<<<NNODES / 16, 256>>>(LN[0], LN[1], LN[2], sc, out);
}

// round 17
// speedup vs baseline: 1.1033x; 1.1033x over previous
#include <cuda_runtime.h>

#define NNODES 4096
#define C      128
#define E      10
#define NI     9
#define NM     9      // 1+3+5 output comps
#define K3     30
#define K2     12
#define K1     4
#define NT3    165    // sorted triples p<=q<=r of 9
#define NT2    45     // sorted pairs
#define MROW   12     // padded m-row stride (ull) -> 96B rows, 16B-aligned
#define OUTW   1152   // C*(1+3+5)
#define NORMF  0.08838834764831845f  // 1/sqrt(128)
#define TC     24     // t-chunk size for c3 fold
#define NCH    7      // ceil(165/24)

typedef unsigned long long ull;

// ---------- packed f32x2 helpers ----------
__device__ __forceinline__ ull fma2(ull a, ull b, ull c) {
    ull d; asm("fma.rn.f32x2 %0, %1, %2, %3;" : "=l"(d) : "l"(a), "l"(b), "l"(c)); return d;
}
__device__ __forceinline__ ull mul2(ull a, ull b) {
    ull d; asm("mul.rn.f32x2 %0, %1, %2;" : "=l"(d) : "l"(a), "l"(b)); return d;
}
__device__ __forceinline__ ull pack2(float a, float b) {
    ull r; asm("mov.b64 %0, {%1,%2};" : "=l"(r) : "r"(__float_as_uint(a)), "r"(__float_as_uint(b))); return r;
}
__device__ __forceinline__ ull dup2(float v) { return pack2(v, v); }
__device__ __forceinline__ void unpack2(ull v, float& a, float& b) {
    unsigned lo, hi; asm("mov.b64 {%0,%1}, %2;" : "=r"(lo), "=r"(hi) : "l"(v));
    a = __uint_as_float(lo); b = __uint_as_float(hi);
}

// ---------- device scratch (static) ----------
__device__ int   g_cnt[E];
__device__ int   g_list[E * NNODES];
__device__ float g_C3[E * C * NM * NT3];
__device__ float g_C2[E * C * NM * NT2];
__device__ float g_C1[E * C * NM * NI];
__device__ float g_res[NNODES * C * NM];   // [b][c][m]

__device__ __forceinline__ void m_to_ld(int m, int& L, int& d) {
    if (m == 0)      { L = 0; d = 0; }
    else if (m < 4)  { L = 1; d = m - 1; }
    else             { L = 2; d = m - 4; }
}

// ---------- 1: fused prep — bucket (10) + chunked c3 fold (630) + c21 fold (90) ----------
__global__ void __launch_bounds__(256) k_prep(
    const float* __restrict__ attrs,
    const float* __restrict__ A0, const float* __restrict__ A1, const float* __restrict__ A2,   // U3
    const float* __restrict__ B0, const float* __restrict__ B1, const float* __restrict__ B2,   // U2
    const float* __restrict__ U1_0, const float* __restrict__ U1_1, const float* __restrict__ U1_2,
    const float* __restrict__ W0, const float* __restrict__ W1, const float* __restrict__ W2,   // W3
    const float* __restrict__ W2_0, const float* __restrict__ W2_1, const float* __restrict__ W2_2,
    const float* __restrict__ W1_0, const float* __restrict__ W1_1, const float* __restrict__ W1_2) {
    __shared__ int   tp[NT3], tq[NT3], tr[NT3];
    __shared__ float sU[TC * K3];     // 2.9 KB (chunked)
    __shared__ int   pp[NT2], pq[NT2];
    __shared__ float sU2[NT2 * K2];
    __shared__ int   scnt;
    int bid = blockIdx.x;
    int tid = threadIdx.x;

    if (bid < E) {
        int e = bid;
        if (tid == 0) scnt = 0;
        __syncthreads();
        for (int b = tid; b < NNODES; b += 256) {
            const float* a = attrs + b * E;
            int am = 0; float best = a[0];
            #pragma unroll
            for (int j = 1; j < E; j++) if (a[j] > best) { best = a[j]; am = j; }
            if (am == e) {
                int pos = atomicAdd(&scnt, 1);
                g_list[e * NNODES + pos] = b;
            }
        }
        __syncthreads();
        if (tid == 0) g_cnt[e] = scnt;
        return;
    }
    if (bid < E + NM * E * NCH) {
        int w = bid - E;
        int chunk = w % NCH;
        int me = w / NCH;
        int m = me % NM, e = me / NM, L, d; m_to_ld(m, L, d);
        int t0 = chunk * TC;
        int tend = (t0 + TC < NT3) ? (t0 + TC) : NT3;
        if (tid == 0) {
            int t = 0;
            for (int q = 0; q < NI; q++)
                for (int r = q; r < NI; r++)
                    for (int p = 0; p <= q; p++) { tp[t] = p; tq[t] = q; tr[t] = r; t++; }
        }
        __syncthreads();
        const float* U = (L == 0) ? A0 : ((L == 1) ? A1 : A2);
        int nsym = (tend - t0) * K3;
        for (int idx = tid; idx < nsym; idx += 256) {
            int t = t0 + idx / K3, k = idx % K3;
            int p = tp[t], q = tq[t], r = tr[t];
            float s = U[(((d*NI + p)*NI + q)*NI + r)*K3 + k]
                    + U[(((d*NI + p)*NI + r)*NI + q)*K3 + k]
                    + U[(((d*NI + q)*NI + p)*NI + r)*K3 + k]
                    + U[(((d*NI + q)*NI + r)*NI + p)*K3 + k]
                    + U[(((d*NI + r)*NI + p)*NI + q)*K3 + k]
                    + U[(((d*NI + r)*NI + q)*NI + p)*K3 + k];
            float div = (p == r) ? 6.f : ((p == q || q == r) ? 2.f : 1.f);
            sU[idx] = s / div;
        }
        __syncthreads();
        int c = tid & 127, sub = tid >> 7;
        const float* W = ((L == 0) ? W0 : ((L == 1) ? W1 : W2)) + e * K3 * C;
        float w3[K3];
        #pragma unroll
        for (int k = 0; k < K3; k++) w3[k] = W[k * C + c];
        float* dst = &g_C3[((e*C + c)*NM + m)*NT3];
        for (int t = t0 + sub; t < tend; t += 2) {
            float a = 0.f;
            #pragma unroll
            for (int k = 0; k < K3; k++) a += sU[(t - t0)*K3 + k] * w3[k];
            dst[t] = a;
        }
        return;
    }
    {
        int w = bid - E - NM * E * NCH;
        int m = w % NM, e = w / NM, L, d; m_to_ld(m, L, d);
        if (tid == 0) {
            int s = 0;
            for (int q = 0; q < NI; q++)
                for (int p = 0; p <= q; p++) { pp[s] = p; pq[s] = q; s++; }
        }
        __syncthreads();
        const float* U2 = (L == 0) ? B0 : ((L == 1) ? B1 : B2);
        for (int idx = tid; idx < NT2 * K2; idx += 256) {
            int s = idx / K2, k = idx % K2;
            int p = pp[s], q = pq[s];
            float v = U2[((d*NI + p)*NI + q)*K2 + k];
            if (p != q) v += U2[((d*NI + q)*NI + p)*K2 + k];
            sU2[idx] = v;
        }
        __syncthreads();
        int c = tid & 127, sub = tid >> 7;
        const float* Wq = ((L == 0) ? W2_0 : ((L == 1) ? W2_1 : W2_2)) + e * K2 * C;
        float w2[K2];
        #pragma unroll
        for (int k = 0; k < K2; k++) w2[k] = Wq[k * C + c];
        float* d2 = &g_C2[((e*C + c)*NM + m)*NT2];
        for (int s = sub; s < NT2; s += 2) {
            float a = 0.f;
            #pragma unroll
            for (int k = 0; k < K2; k++) a += sU2[s*K2 + k] * w2[k];
            d2[s] = a;
        }
        if (sub == 0) {
            const float* Wl = ((L == 0) ? W1_0 : ((L == 1) ? W1_1 : W1_2)) + e * K1 * C;
            const float* U1 = ((L == 0) ? U1_0 : ((L == 1) ? U1_1 : U1_2)) + d * NI * K1;
            float w1[K1];
            #pragma unroll
            for (int k = 0; k < K1; k++) w1[k] = Wl[k * C + c];
            float* d1 = &g_C1[((e*C + c)*NM + m)*NI];
            #pragma unroll
            for (int i = 0; i < NI; i++) {
                float a = 0.f;
                #pragma unroll
                for (int k = 0; k < K1; k++) a += U1[i*K1 + k] * w1[k];
                d1[i] = a;
            }
        }
    }
}

// ---------- 2: main contraction — 4 nodes/thread, 128 threads, [t][m] rows, cap 170 regs ----------
__global__ void __launch_bounds__(128, 3) k_main(const float* __restrict__ nf) {
    __shared__ __align__(16) ull s3t[NT3 * MROW];  // 15.5 KB
    __shared__ __align__(16) ull s2t[NT2 * MROW];  //  4.2 KB
    __shared__ __align__(16) ull s1t[NI  * MROW];  //  0.84 KB
    int c = blockIdx.x, e = blockIdx.y;
    {
        const float* g3 = g_C3 + (e*C + c) * NM * NT3;
        const float* g2 = g_C2 + (e*C + c) * NM * NT2;
        const float* g1 = g_C1 + (e*C + c) * NM * NI;
        for (int i = threadIdx.x; i < NM*NT3; i += 128) {
            int m = i / NT3, t = i % NT3;
            s3t[t*MROW + m] = dup2(g3[i]);
        }
        for (int i = threadIdx.x; i < NM*NT2; i += 128) {
            int m = i / NT2, s = i % NT2;
            s2t[s*MROW + m] = dup2(g2[i]);
        }
        for (int i = threadIdx.x; i < NM*NI; i += 128) {
            int m = i / NI, p = i % NI;
            s1t[p*MROW + m] = dup2(g1[i]);
        }
    }
    __syncthreads();
    int cnt = g_cnt[e];
    const int* lst = g_list + e * NNODES;

    for (int base = 0; base < cnt; base += 512) {
        int i0 = base + threadIdx.x;
        bool v0 = i0 < cnt, v1 = (i0+128) < cnt, v2 = (i0+256) < cnt, v3 = (i0+384) < cnt;
        int b0 = v0 ? lst[i0]     : 0;
        int b1 = v1 ? lst[i0+128] : 0;
        int b2 = v2 ? lst[i0+256] : 0;
        int b3 = v3 ? lst[i0+384] : 0;
        const float* p0 = nf + (b0*C + c) * NI;
        const float* p1 = nf + (b1*C + c) * NI;
        const float* p2 = nf + (b2*C + c) * NI;
        const float* p3 = nf + (b3*C + c) * NI;

        ull xa[9], xb[9];
        #pragma unroll
        for (int n = 0; n < 9; n++) {
            xa[n] = pack2(v0 ? p0[n] : 0.f, v1 ? p1[n] : 0.f);
            xb[n] = pack2(v2 ? p2[n] : 0.f, v3 ? p3[n] : 0.f);
        }
        ull aA[9], aB[9];
        #pragma unroll
        for (int m = 0; m < 9; m++) { aA[m] = 0ull; aB[m] = 0ull; }

        // linear
        #pragma unroll
        for (int p = 0; p < 9; p++) {
            const ulonglong2* cp = reinterpret_cast<const ulonglong2*>(&s1t[p*MROW]);
            ulonglong2 c01 = cp[0], c23 = cp[1], c45 = cp[2], c67 = cp[3];
            ull c8 = s1t[p*MROW + 8];
            ull mA = xa[p], mB = xb[p];
            aA[0] = fma2(c01.x, mA, aA[0]); aB[0] = fma2(c01.x, mB, aB[0]);
            aA[1] = fma2(c01.y, mA, aA[1]); aB[1] = fma2(c01.y, mB, aB[1]);
            aA[2] = fma2(c23.x, mA, aA[2]); aB[2] = fma2(c23.x, mB, aB[2]);
            aA[3] = fma2(c23.y, mA, aA[3]); aB[3] = fma2(c23.y, mB, aB[3]);
            aA[4] = fma2(c45.x, mA, aA[4]); aB[4] = fma2(c45.x, mB, aB[4]);
            aA[5] = fma2(c45.y, mA, aA[5]); aB[5] = fma2(c45.y, mB, aB[5]);
            aA[6] = fma2(c67.x, mA, aA[6]); aB[6] = fma2(c67.x, mB, aB[6]);
            aA[7] = fma2(c67.y, mA, aA[7]); aB[7] = fma2(c67.y, mB, aB[7]);
            aA[8] = fma2(c8,    mA, aA[8]); aB[8] = fma2(c8,    mB, aB[8]);
        }
        // quadratic
        {
            int s = 0;
            #pragma unroll
            for (int q = 0; q < 9; q++)
                #pragma unroll
                for (int p = 0; p <= q; p++) {
                    ull mA = mul2(xa[p], xa[q]);
                    ull mB = mul2(xb[p], xb[q]);
                    const ulonglong2* cp = reinterpret_cast<const ulonglong2*>(&s2t[s*MROW]);
                    ulonglong2 c01 = cp[0], c23 = cp[1], c45 = cp[2], c67 = cp[3];
                    ull c8 = s2t[s*MROW + 8];
                    aA[0] = fma2(c01.x, mA, aA[0]); aB[0] = fma2(c01.x, mB, aB[0]);
                    aA[1] = fma2(c01.y, mA, aA[1]); aB[1] = fma2(c01.y, mB, aB[1]);
                    aA[2] = fma2(c23.x, mA, aA[2]); aB[2] = fma2(c23.x, mB, aB[2]);
                    aA[3] = fma2(c23.y, mA, aA[3]); aB[3] = fma2(c23.y, mB, aB[3]);
                    aA[4] = fma2(c45.x, mA, aA[4]); aB[4] = fma2(c45.x, mB, aB[4]);
                    aA[5] = fma2(c45.y, mA, aA[5]); aB[5] = fma2(c45.y, mB, aB[5]);
                    aA[6] = fma2(c67.x, mA, aA[6]); aB[6] = fma2(c67.x, mB, aB[6]);
                    aA[7] = fma2(c67.y, mA, aA[7]); aB[7] = fma2(c67.y, mB, aB[7]);
                    aA[8] = fma2(c8,    mA, aA[8]); aB[8] = fma2(c8,    mB, aB[8]);
                    s++;
                }
        }
        // cubic
        {
            int t = 0;
            #pragma unroll
            for (int q = 0; q < 9; q++)
                #pragma unroll
                for (int r = q; r < 9; r++) {
                    ull wA = mul2(xa[q], xa[r]);
                    ull wB = mul2(xb[q], xb[r]);
                    #pragma unroll
                    for (int p = 0; p <= q; p++) {
                        ull mA = mul2(xa[p], wA);
                        ull mB = mul2(xb[p], wB);
                        const ulonglong2* cp = reinterpret_cast<const ulonglong2*>(&s3t[t*MROW]);
                        ulonglong2 c01 = cp[0], c23 = cp[1], c45 = cp[2], c67 = cp[3];
                        ull c8 = s3t[t*MROW + 8];
                        aA[0] = fma2(c01.x, mA, aA[0]); aB[0] = fma2(c01.x, mB, aB[0]);
                        aA[1] = fma2(c01.y, mA, aA[1]); aB[1] = fma2(c01.y, mB, aB[1]);
                        aA[2] = fma2(c23.x, mA, aA[2]); aB[2] = fma2(c23.x, mB, aB[2]);
                        aA[3] = fma2(c23.y, mA, aA[3]); aB[3] = fma2(c23.y, mB, aB[3]);
                        aA[4] = fma2(c45.x, mA, aA[4]); aB[4] = fma2(c45.x, mB, aB[4]);
                        aA[5] = fma2(c45.y, mA, aA[5]); aB[5] = fma2(c45.y, mB, aB[5]);
                        aA[6] = fma2(c67.x, mA, aA[6]); aB[6] = fma2(c67.x, mB, aB[6]);
                        aA[7] = fma2(c67.y, mA, aA[7]); aB[7] = fma2(c67.y, mB, aB[7]);
                        aA[8] = fma2(c8,    mA, aA[8]); aB[8] = fma2(c8,    mB, aB[8]);
                        t++;
                    }
                }
        }
        // store res[b][c][m]
        #pragma unroll
        for (int m = 0; m < 9; m++) {
            float f0, f1, f2, f3;
            unpack2(aA[m], f0, f1); unpack2(aB[m], f2, f3);
            if (v0) g_res[(b0*C + c)*NM + m] = f0;
            if (v1) g_res[(b1*C + c)*NM + m] = f1;
            if (v2) g_res[(b2*C + c)*NM + m] = f2;
            if (v3) g_res[(b3*C + c)*NM + m] = f3;
        }
    }
}

// ---------- 3: channel mix — R13-proven 128-thread version ----------
__global__ void __launch_bounds__(128) k_mix(const float* __restrict__ lin0,
                                             const float* __restrict__ lin1,
                                             const float* __restrict__ lin2,
                                             const float* __restrict__ sc,
                                             float* __restrict__ out) {
    __shared__ ull sres[64 * 9 * 4];   // [c_local*9+m][j], 18 KB
    int f = threadIdx.x;
    int bb = blockIdx.x * 8;
    ull acc[9][4];
    #pragma unroll
    for (int m = 0; m < 9; m++)
        #pragma unroll
        for (int j = 0; j < 4; j++) acc[m][j] = 0ull;

    for (int ct = 0; ct < 2; ct++) {
        int c0 = ct * 64;
        __syncthreads();
        for (int idx = threadIdx.x; idx < 64*9*4; idx += 128) {
            int j  = idx / 576;
            int cm = idx % 576;
            int n0 = bb + 2*j;
            float a = g_res[(n0    *C + c0)*NM + cm];
            float b = g_res[((n0+1)*C + c0)*NM + cm];
            sres[cm*4 + j] = pack2(a, b);
        }
        __syncthreads();
        for (int cl = 0; cl < 64; cl++) {
            int cc = c0 + cl;
            ull l0 = dup2(lin0[cc*C + f]);
            ull l1 = dup2(lin1[cc*C + f]);
            ull l2 = dup2(lin2[cc*C + f]);
            #pragma unroll
            for (int m = 0; m < 9; m++) {
                ull lv = (m == 0) ? l0 : ((m < 4) ? l1 : l2);
                const ulonglong2* sp = reinterpret_cast<const ulonglong2*>(&sres[(cl*9 + m)*4]);
                ulonglong2 va = sp[0];
                ulonglong2 vb = sp[1];
                acc[m][0] = fma2(lv, va.x, acc[m][0]);
                acc[m][1] = fma2(lv, va.y, acc[m][1]);
                acc[m][2] = fma2(lv, vb.x, acc[m][2]);
                acc[m][3] = fma2(lv, vb.y, acc[m][3]);
            }
        }
    }
    #pragma unroll
    for (int m = 0; m < 9; m++) {
        int col = (m == 0) ? f : ((m < 4) ? (128 + f*3 + (m-1)) : (512 + f*5 + (m-4)));
        #pragma unroll
        for (int j = 0; j < 4; j++) {
            float v0, v1; unpack2(acc[m][j], v0, v1);
            int n0 = bb + 2*j;
            out[n0*OUTW + col]     = v0 * NORMF + sc[n0*OUTW + col];
            out[(n0+1)*OUTW + col] = v1 * NORMF + sc[(n0+1)*OUTW + col];
        }
    }
}

extern "C" void kernel_launch(void* const* d_in, const int* in_sizes, int n_in,
                              void* d_out, int out_size) {
    (void)in_sizes; (void)n_in; (void)out_size;
    const float* nf    = (const float*)d_in[0];
    const float* sc    = (const float*)d_in[1];
    const float* attrs = (const float*)d_in[2];
    const float* U3[3]; const float* U2[3]; const float* U1[3];
    const float* W3[3]; const float* W2[3]; const float* W1[3]; const float* LN[3];
    for (int L = 0; L < 3; L++) {
        int b = 3 + 7*L;
        U3[L] = (const float*)d_in[b+0];
        U2[L] = (const float*)d_in[b+1];
        U1[L] = (const float*)d_in[b+2];
        W3[L] = (const float*)d_in[b+3];
        W2[L] = (const float*)d_in[b+4];
        W1[L] = (const float*)d_in[b+5];
        LN[L] = (const float*)d_in[b+6];
    }
    float* out = (float*)d_out;

    k_prep<<<E + NM * E * NCH + NM * E, 256>>>(attrs,
                                    U3[0], U3[1], U3[2],
                                    U2[0], U2[1], U2[2],
                                    U1[0], U1[1], U1[2],
                                    W3[0], W3[1], W3[2],
                                    W2[0], W2[1], W2[2],
                                    W1[0], W1[1], W1[2]);
    k_main<<<dim3(C, E), 128>>>(nf);
    k_mix<<<NNODES / 8, 128>>>(LN[0], LN[1], LN[2], sc, out);
}